// round 11
// baseline (speedup 1.0000x reference)
#include <cuda_runtime.h>
#include <cstdint>

#define NPTS 65536
#define KC   4096
#define DIM  128
#define BN   128          // n rows per CTA
#define BK   64           // centroids per k-tile
#define KHALF 2048        // k range per CTA
#define NT   (KHALF / BK) // 32 tiles

// Device scratch: u32-packed int8 slice planes (4 s8 per u32, k-ascending)
__device__ uint32_t g_A0[NPTS * 32];
__device__ uint32_t g_A1[NPTS * 32];
__device__ uint32_t g_A2[NPTS * 32];
__device__ uint32_t g_B0[KC * 32];
__device__ uint32_t g_B1[KC * 32];
__device__ uint32_t g_B2[KC * 32];
__device__ float g_sa[NPTS];          // per-row scale of latent
__device__ float g_sb[KC];            // per-row scale of coords
__device__ float g_c2[KC];            // exact ||c||^2
__device__ unsigned long long g_best[NPTS];

// ---------------------------------------------------------------------------
__device__ __forceinline__ uint32_t smem_u32(const void* p) {
    uint32_t a;
    asm("{ .reg .u64 t; cvta.to.shared.u64 t, %1; cvt.u32.u64 %0, t; }"
        : "=r"(a) : "l"(p));
    return a;
}
__device__ __forceinline__ uint32_t fkey(float f) {      // order-preserving
    uint32_t u = __float_as_uint(f);
    return (u & 0x80000000u) ? ~u : (u | 0x80000000u);
}
#define LDSM_X4(r0, r1, r2, r3, addr) \
    asm volatile("ldmatrix.sync.aligned.m8n8.x4.shared.b16 {%0,%1,%2,%3}, [%4];" \
                 : "=r"(r0), "=r"(r1), "=r"(r2), "=r"(r3) : "r"(addr))
#define MMA_S8(c, a, b0v, b1v) \
    asm volatile("mma.sync.aligned.m16n8k32.row.col.s32.s8.s8.s32 " \
                 "{%0,%1,%2,%3}, {%4,%5,%6,%7}, {%8,%9}, {%0,%1,%2,%3};" \
                 : "+r"((c)[0]), "+r"((c)[1]), "+r"((c)[2]), "+r"((c)[3]) \
                 : "r"((a)[0]), "r"((a)[1]), "r"((a)[2]), "r"((a)[3]), \
                   "r"(b0v), "r"(b1v))
__device__ __forceinline__ void cp16(uint32_t dst, const void* src) {
    asm volatile("cp.async.cg.shared.global [%0], [%1], 16;"
                 :: "r"(dst), "l"(src));
}
#define CP_COMMIT() asm volatile("cp.async.commit_group;" ::: "memory")
#define CP_WAIT0()  asm volatile("cp.async.wait_group 0;" ::: "memory")

__device__ __forceinline__ uint32_t pack4(int a, int b, int c, int d) {
    return (uint32_t)(a & 0xFF) | ((uint32_t)(b & 0xFF) << 8) |
           ((uint32_t)(c & 0xFF) << 16) | ((uint32_t)(d & 0xFF) << 24);
}

// ---------------------------------------------------------------------------
// Quantization prologues: warp per row. s = 2^(e-6) where m = f*2^e (frexp),
// slices X0,X1,X2 in [-64,64]: a = s*(X0 + X1/128 + X2/16384 + eps/16384).
// ---------------------------------------------------------------------------
__device__ __forceinline__ void quant_row(float4 v, float inv,
                                          uint32_t& p0, uint32_t& p1,
                                          uint32_t& p2) {
    float va[4] = {v.x, v.y, v.z, v.w};
    int X0[4], X1[4], X2[4];
    #pragma unroll
    for (int j = 0; j < 4; ++j) {
        float x  = va[j] * inv;
        float f0 = rintf(x);        X0[j] = (int)f0;
        float r1 = (x - f0) * 128.f;
        float f1 = rintf(r1);       X1[j] = (int)f1;
        float r2 = (r1 - f1) * 128.f;
        X2[j] = (int)rintf(r2);
    }
    p0 = pack4(X0[0], X0[1], X0[2], X0[3]);
    p1 = pack4(X1[0], X1[1], X1[2], X1[3]);
    p2 = pack4(X2[0], X2[1], X2[2], X2[3]);
}
__global__ void quant_lat_kernel(const float* __restrict__ in) {
    int row  = blockIdx.x * 8 + (threadIdx.x >> 5);
    int lane = threadIdx.x & 31;
    float4 v = ((const float4*)(in + (size_t)row * DIM))[lane];
    float m = fmaxf(fmaxf(fabsf(v.x), fabsf(v.y)), fmaxf(fabsf(v.z), fabsf(v.w)));
    #pragma unroll
    for (int o = 16; o; o >>= 1) m = fmaxf(m, __shfl_xor_sync(~0u, m, o));
    float s, inv;
    if (m == 0.f) { s = 1.f; inv = 1.f; }
    else { int e; frexpf(m, &e); s = ldexpf(1.f, e - 6); inv = ldexpf(1.f, 6 - e); }
    uint32_t p0, p1, p2;
    quant_row(v, inv, p0, p1, p2);
    g_A0[(size_t)row * 32 + lane] = p0;
    g_A1[(size_t)row * 32 + lane] = p1;
    g_A2[(size_t)row * 32 + lane] = p2;
    if (lane == 0) g_sa[row] = s;
}
__global__ void quant_coo_kernel(const float* __restrict__ in) {
    int row  = blockIdx.x * 8 + (threadIdx.x >> 5);
    int lane = threadIdx.x & 31;
    float4 v = ((const float4*)(in + (size_t)row * DIM))[lane];
    float c2 = fmaf(v.x, v.x, fmaf(v.y, v.y, fmaf(v.z, v.z, v.w * v.w)));
    float m = fmaxf(fmaxf(fabsf(v.x), fabsf(v.y)), fmaxf(fabsf(v.z), fabsf(v.w)));
    #pragma unroll
    for (int o = 16; o; o >>= 1) {
        m  = fmaxf(m, __shfl_xor_sync(~0u, m, o));
        c2 += __shfl_xor_sync(~0u, c2, o);
    }
    float s, inv;
    if (m == 0.f) { s = 1.f; inv = 1.f; }
    else { int e; frexpf(m, &e); s = ldexpf(1.f, e - 6); inv = ldexpf(1.f, 6 - e); }
    uint32_t p0, p1, p2;
    quant_row(v, inv, p0, p1, p2);
    g_B0[(size_t)row * 32 + lane] = p0;
    g_B1[(size_t)row * 32 + lane] = p1;
    g_B2[(size_t)row * 32 + lane] = p2;
    if (lane == 0) { g_sb[row] = s; g_c2[row] = c2; }
}
__global__ void init_best_kernel() {
    int i = blockIdx.x * blockDim.x + threadIdx.x;
    if (i < NPTS) g_best[i] = 0xFFFFFFFFFFFFFFFFull;
}
__global__ void final_kernel(float* __restrict__ out) {
    int i = blockIdx.x * blockDim.x + threadIdx.x;
    if (i < NPTS) out[i] = (float)(uint32_t)(g_best[i] & 0xFFFFFFFFull);
}

// ---------------------------------------------------------------------------
// Main: IMMA s8 3-slice 6-pass GEMM + fused argmin.
// 256 threads = 8 warps, grid 4(M) x 2(N); warp tile 32(M) x 32(N), BK=64.
// smem: A slices @0/16K/32K (128 rows x 128B); B @48K + st*24K + sl*8K
// (64 rows x 128B). Row = 8 granules of 16B, swizzle g ^= (row & 7).
// ---------------------------------------------------------------------------
__global__ __launch_bounds__(256, 1) void nn_imma_kernel() {
    extern __shared__ char smem[];
    const uint32_t sbase = smem_u32(smem);

    const int tid = threadIdx.x;
    const int L   = tid & 31;
    const int wid = tid >> 5;
    const int wm  = wid & 3;        // 4 M groups (32 rows)
    const int wn  = wid >> 2;       // 2 N groups (32 cols)
    const int n0  = (blockIdx.x >> 1) * BN;
    const int kb  = (blockIdx.x & 1) * KHALF;

    // ---- stage A slices once ----
    {
        const uint32_t* gA[3] = {g_A0, g_A1, g_A2};
        #pragma unroll
        for (int s = 0; s < 3; ++s)
            #pragma unroll
            for (int it = 0; it < 4; ++it) {
                int Gi = tid + it * 256;            // 0..1023 granules
                int row = Gi >> 3, g = Gi & 7;
                uint4 v = *(const uint4*)(gA[s] + (size_t)(n0 + row) * 32 + g * 4);
                *(uint4*)(smem + s * 16384 + row * 128 + ((g ^ (row & 7)) << 4)) = v;
            }
    }

    auto stage_b = [&](int st, int k0) {
        #pragma unroll
        for (int s = 0; s < 3; ++s) {
            const uint32_t* gb = (s == 0) ? g_B0 : (s == 1) ? g_B1 : g_B2;
            #pragma unroll
            for (int it = 0; it < 2; ++it) {
                int Gi = tid + it * 256;            // 0..511 granules
                int row = Gi >> 3, g = Gi & 7;
                uint32_t dst = sbase + 49152 + st * 24576 + s * 8192 +
                               row * 128 + ((g ^ (row & 7)) << 4);
                cp16(dst, gb + (size_t)(k0 + row) * 32 + g * 4);
            }
        }
    };
    stage_b(0, kb);
    CP_COMMIT();

    // ldmatrix lane constants (b16-granule view of s8: 2 s8 = 1 b16)
    const int aRow = (L & 7) + 8 * ((L >> 3) & 1);
    const int aG   = L >> 4;
    const int sxa  = L & 7;
    const int bRow = (L & 7) + 8 * (L >> 4);
    const int bG   = (L >> 3) & 1;
    const int sxb  = L & 7;
    uint32_t aAddrBase[2];
    #pragma unroll
    for (int bi = 0; bi < 2; ++bi)
        aAddrBase[bi] = sbase + (32 * wm + 16 * bi + aRow) * 128;

    // per-thread row scale factors (rows: 32wm + 16bi + 8h + L>>2)
    float ksa[2][2];
    #pragma unroll
    for (int bi = 0; bi < 2; ++bi)
        #pragma unroll
        for (int h = 0; h < 2; ++h)
            ksa[bi][h] = g_sa[n0 + 32 * wm + 16 * bi + 8 * h + (L >> 2)] *
                         (-2.0f / 16384.0f);

    float rval[4];
    int   ridx[4];
    #pragma unroll
    for (int i = 0; i < 4; ++i) { rval[i] = 3.0e38f; ridx[i] = 0; }

    // pass table: (ai, bj) grouped by weight w = ai+bj
    const int PA[6] = {0, 0, 1, 1, 2, 0};
    const int PB[6] = {0, 1, 0, 1, 0, 2};
    const int PW[6] = {0, 1, 1, 2, 2, 2};

    for (int kt = 0; kt < NT; ++kt) {
        const int st = kt & 1;
        const int k0 = kb + kt * BK;

        CP_WAIT0();
        __syncthreads();
        if (kt + 1 < NT) { stage_b(st ^ 1, k0 + BK); CP_COMMIT(); }

        int accW[3][2][4][4];
        #pragma unroll
        for (int w = 0; w < 3; ++w)
            #pragma unroll
            for (int bi = 0; bi < 2; ++bi)
                #pragma unroll
                for (int nb = 0; nb < 4; ++nb)
                    #pragma unroll
                    for (int c = 0; c < 4; ++c) accW[w][bi][nb][c] = 0;

        const uint32_t bAddr0 = sbase + 49152 + st * 24576;

        #pragma unroll
        for (int kk = 0; kk < 4; ++kk) {           // k32 per step, K=128
            uint32_t a[3][2][4];
            #pragma unroll
            for (int sl = 0; sl < 3; ++sl)
                #pragma unroll
                for (int bi = 0; bi < 2; ++bi) {
                    uint32_t ad = aAddrBase[bi] + sl * 16384 +
                                  (((2 * kk + aG) ^ sxa) << 4);
                    LDSM_X4(a[sl][bi][0], a[sl][bi][1], a[sl][bi][2], a[sl][bi][3], ad);
                }
            uint32_t b[3][2][4];                   // [slice][n16-group]
            #pragma unroll
            for (int sl = 0; sl < 3; ++sl)
                #pragma unroll
                for (int i2 = 0; i2 < 2; ++i2) {
                    uint32_t bd = bAddr0 + sl * 8192 +
                                  (32 * wn + 16 * i2 + bRow) * 128 +
                                  (((2 * kk + bG) ^ sxb) << 4);
                    LDSM_X4(b[sl][i2][0], b[sl][i2][1], b[sl][i2][2], b[sl][i2][3], bd);
                }
            #pragma unroll
            for (int p = 0; p < 6; ++p)
                #pragma unroll
                for (int bi = 0; bi < 2; ++bi)
                    #pragma unroll
                    for (int nb = 0; nb < 4; ++nb) {
                        const uint32_t* q = b[PB[p]][nb >> 1];
                        if (nb & 1) MMA_S8(accW[PW[p]][bi][nb], a[PA[p]][bi], q[2], q[3]);
                        else        MMA_S8(accW[PW[p]][bi][nb], a[PA[p]][bi], q[0], q[1]);
                    }
        }

        // ---- epilogue: T = (W0<<14) + (W1<<7) + W2 (exact s64);
        //      score = c2 - 2*sA*sB*T/16384; strict '<' = first occurrence ----
        #pragma unroll
        for (int bi = 0; bi < 2; ++bi)
            #pragma unroll
            for (int nb = 0; nb < 4; ++nb) {
                int kc = k0 + 32 * wn + 8 * nb + 2 * (L & 3);
                float2 c2p = __ldg((const float2*)(g_c2 + kc));
                float2 sbp = __ldg((const float2*)(g_sb + kc));
                #pragma unroll
                for (int h = 0; h < 2; ++h) {
                    int r = bi * 2 + h;
                    long long T0 = ((long long)accW[0][bi][nb][h * 2] << 14) +
                                   ((long long)accW[1][bi][nb][h * 2] << 7) +
                                   accW[2][bi][nb][h * 2];
                    long long T1 = ((long long)accW[0][bi][nb][h * 2 + 1] << 14) +
                                   ((long long)accW[1][bi][nb][h * 2 + 1] << 7) +
                                   accW[2][bi][nb][h * 2 + 1];
                    float s0 = fmaf((float)T0 * ksa[bi][h], sbp.x, c2p.x);
                    float s1 = fmaf((float)T1 * ksa[bi][h], sbp.y, c2p.y);
                    if (s0 < rval[r]) { rval[r] = s0; ridx[r] = kc; }
                    if (s1 < rval[r]) { rval[r] = s1; ridx[r] = kc + 1; }
                }
            }
    }

    // ---- intra-CTA merge (8 slots per row), then global atomicMin ----
    __syncthreads();
    float* rv = (float*)smem;                    // reuse A region
    int*   ri = (int*)(smem + 128 * 8 * 4);
    #pragma unroll
    for (int bi = 0; bi < 2; ++bi)
        #pragma unroll
        for (int h = 0; h < 2; ++h) {
            int row  = 32 * wm + 16 * bi + 8 * h + (L >> 2);
            int slot = wn * 4 + (L & 3);
            rv[row * 8 + slot] = rval[bi * 2 + h];
            ri[row * 8 + slot] = ridx[bi * 2 + h];
        }
    __syncthreads();
    if (tid < BN) {
        float bv = rv[tid * 8];
        int   bi = ri[tid * 8];
        #pragma unroll
        for (int c = 1; c < 8; ++c) {
            float v  = rv[tid * 8 + c];
            int   id = ri[tid * 8 + c];
            if (v < bv || (v == bv && id < bi)) { bv = v; bi = id; }
        }
        unsigned long long key =
            ((unsigned long long)fkey(bv) << 32) | (unsigned int)bi;
        atomicMin(&g_best[n0 + tid], key);
    }
}

// ---------------------------------------------------------------------------
extern "C" void kernel_launch(void* const* d_in, const int* in_sizes, int n_in,
                              void* d_out, int out_size) {
    const float* latent;
    const float* coords;
    if (in_sizes[0] == NPTS * DIM) {
        latent = (const float*)d_in[0];
        coords = (const float*)d_in[1];
    } else {
        latent = (const float*)d_in[1];
        coords = (const float*)d_in[0];
    }
    float* out = (float*)d_out;

    const int smem_bytes = 49152 + 2 * 24576;   // A 48K + B 2x24K = 96K
    cudaFuncSetAttribute(nn_imma_kernel,
                         cudaFuncAttributeMaxDynamicSharedMemorySize, smem_bytes);

    init_best_kernel<<<NPTS / 256, 256>>>();
    quant_lat_kernel<<<NPTS / 8, 256>>>(latent);
    quant_coo_kernel<<<KC / 8, 256>>>(coords);
    nn_imma_kernel<<<(NPTS / BN) * 2, 256, smem_bytes>>>();
    final_kernel<<<NPTS / 256, 256>>>(out);
}

// round 12
// speedup vs baseline: 4.7526x; 4.7526x over previous
#include <cuda_runtime.h>
#include <cuda_bf16.h>
#include <cstdint>

#define NPTS 65536
#define KC   4096
#define DIM  128
#define BN   128
#define BK   128
#define NT   (KC / BK)    // 32 tiles, full k-range per CTA
#define CAP  (1 << 24)    // candidate list capacity (16M)

// Device scratch (allocation-free rule)
__device__ __nv_bfloat16 g_a0[NPTS * DIM];
__device__ __nv_bfloat16 g_b0[KC * DIM];
__device__ __align__(16) float2 g_an[NPTS];  // {2||a1||, 2||a0||}
__device__ __align__(16) float2 g_bn[KC];    // {||b||, ||b1||}
__device__ __align__(8)  float  g_c2[KC];    // exact ||b||^2
__device__ float g_bmax[2];                  // {max||b||, max||b1||}
__device__ float g_bestval[NPTS];            // phase-1 approx best
__device__ unsigned long long g_best[NPTS];  // (fkey(score)<<32)|idx
__device__ int g_cnt[1];
__device__ uint32_t g_list[CAP];             // (n<<12)|k

// ---------------------------------------------------------------------------
__device__ __forceinline__ uint32_t smem_u32(const void* p) {
    uint32_t a;
    asm("{ .reg .u64 t; cvta.to.shared.u64 t, %1; cvt.u32.u64 %0, t; }"
        : "=r"(a) : "l"(p));
    return a;
}
__device__ __forceinline__ uint32_t fkey(float f) {      // order-preserving
    uint32_t u = __float_as_uint(f);
    return (u & 0x80000000u) ? ~u : (u | 0x80000000u);
}
#define LDSM_X4(r0, r1, r2, r3, addr) \
    asm volatile("ldmatrix.sync.aligned.m8n8.x4.shared.b16 {%0,%1,%2,%3}, [%4];" \
                 : "=r"(r0), "=r"(r1), "=r"(r2), "=r"(r3) : "r"(addr))
#define MMA_BF16(c, a, b0v, b1v) \
    asm volatile("mma.sync.aligned.m16n8k16.row.col.f32.bf16.bf16.f32 " \
                 "{%0,%1,%2,%3}, {%4,%5,%6,%7}, {%8,%9}, {%0,%1,%2,%3};" \
                 : "+f"((c)[0]), "+f"((c)[1]), "+f"((c)[2]), "+f"((c)[3]) \
                 : "r"((a)[0]), "r"((a)[1]), "r"((a)[2]), "r"((a)[3]), \
                   "r"(b0v), "r"(b1v))
__device__ __forceinline__ void cp16(uint32_t dst, const void* src) {
    asm volatile("cp.async.cg.shared.global [%0], [%1], 16;"
                 :: "r"(dst), "l"(src));
}
#define CP_COMMIT() asm volatile("cp.async.commit_group;" ::: "memory")
#define CP_WAIT0()  asm volatile("cp.async.wait_group 0;" ::: "memory")

// ---------------------------------------------------------------------------
// Prologues: warp per row. a0 = bf16(a); a1 = a - a0 (EXACT fp32 residual).
// ---------------------------------------------------------------------------
__global__ void prep_a(const float* __restrict__ in) {
    int row  = blockIdx.x * 8 + (threadIdx.x >> 5);
    int lane = threadIdx.x & 31;
    float4 v = ((const float4*)(in + (size_t)row * DIM))[lane];
    float va[4] = {v.x, v.y, v.z, v.w};
    __nv_bfloat16 h[4];
    float n0 = 0.f, n1 = 0.f;
    #pragma unroll
    for (int j = 0; j < 4; ++j) {
        h[j] = __float2bfloat16(va[j]);
        float a0 = __bfloat162float(h[j]);
        float r  = va[j] - a0;            // exact
        n0 = fmaf(a0, a0, n0);
        n1 = fmaf(r, r, n1);
    }
    *(uint2*)(g_a0 + (size_t)row * DIM + lane * 4) = *(const uint2*)h;
    #pragma unroll
    for (int o = 16; o; o >>= 1) {
        n0 += __shfl_xor_sync(~0u, n0, o);
        n1 += __shfl_xor_sync(~0u, n1, o);
    }
    if (lane == 0) g_an[row] = make_float2(2.f * sqrtf(n1), 2.f * sqrtf(n0));
}
__global__ void prep_b(const float* __restrict__ in) {
    int row  = blockIdx.x * 8 + (threadIdx.x >> 5);
    int lane = threadIdx.x & 31;
    float4 v = ((const float4*)(in + (size_t)row * DIM))[lane];
    float va[4] = {v.x, v.y, v.z, v.w};
    __nv_bfloat16 h[4];
    float nb = 0.f, n1 = 0.f;
    #pragma unroll
    for (int j = 0; j < 4; ++j) {
        h[j] = __float2bfloat16(va[j]);
        float b0 = __bfloat162float(h[j]);
        float r  = va[j] - b0;            // exact
        nb = fmaf(va[j], va[j], nb);      // full ||b||^2
        n1 = fmaf(r, r, n1);
    }
    *(uint2*)(g_b0 + (size_t)row * DIM + lane * 4) = *(const uint2*)h;
    #pragma unroll
    for (int o = 16; o; o >>= 1) {
        nb += __shfl_xor_sync(~0u, nb, o);
        n1 += __shfl_xor_sync(~0u, n1, o);
    }
    if (lane == 0) {
        g_c2[row] = nb;
        g_bn[row] = make_float2(sqrtf(nb), sqrtf(n1));
    }
}
__global__ void reduce_kernel() {
    __shared__ float s0[512], s1[512];
    int t = threadIdx.x;
    float m0 = 0.f, m1 = 0.f;
    for (int k = t; k < KC; k += 512) {
        float2 b = g_bn[k];
        m0 = fmaxf(m0, b.x);
        m1 = fmaxf(m1, b.y);
    }
    s0[t] = m0; s1[t] = m1;
    __syncthreads();
    for (int o = 256; o; o >>= 1) {
        if (t < o) {
            s0[t] = fmaxf(s0[t], s0[t + o]);
            s1[t] = fmaxf(s1[t], s1[t + o]);
        }
        __syncthreads();
    }
    if (t == 0) { g_bmax[0] = s0[0]; g_bmax[1] = s1[0]; g_cnt[0] = 0; }
}
__global__ void init_best_kernel() {
    int i = blockIdx.x * blockDim.x + threadIdx.x;
    if (i < NPTS) g_best[i] = 0xFFFFFFFFFFFFFFFFull;
}
__global__ void final_kernel(float* __restrict__ out) {
    int i = blockIdx.x * blockDim.x + threadIdx.x;
    if (i < NPTS) out[i] = (float)(uint32_t)(g_best[i] & 0xFFFFFFFFull);
}

// ---------------------------------------------------------------------------
// Phase GEMM: 1-pass a0*b0 HMMA over full K=4096. 256 thr = 8 warps, 4(M)x2(N),
// warp tile 32x64. smem: A @0 (32K), B double-buffer @32K/64K (96 KB total).
// PHASE=1: track per-row min value -> g_bestval.
// PHASE=2: recompute identical scores; push (n,k) with s <= best + margin.
// ---------------------------------------------------------------------------
template <int PHASE>
__global__ __launch_bounds__(256) void phase_kernel() {
    extern __shared__ char smem[];
    const uint32_t sbase = smem_u32(smem);

    const int tid = threadIdx.x;
    const int L   = tid & 31;
    const int wid = tid >> 5;
    const int wm  = wid & 3;
    const int wn  = wid >> 2;
    const int n0  = blockIdx.x * BN;

    // stage A (plane 0) once: 128 rows x 256B, swizzled
    #pragma unroll
    for (int it = 0; it < 8; ++it) {
        int Gi = tid + it * 256;
        int row = Gi >> 4, g = Gi & 15;
        uint4 v = *((const uint4*)(g_a0 + (size_t)(n0 + row) * DIM) + g);
        *(uint4*)(smem + row * 256 + ((g ^ (row & 7)) << 4)) = v;
    }

    auto stage_b = [&](int st, int k0) {
        #pragma unroll
        for (int it = 0; it < 8; ++it) {
            int Gi = tid + it * 256;
            int row = Gi >> 4, g = Gi & 15;
            uint32_t dst = sbase + 32768 + st * 32768 +
                           row * 256 + ((g ^ (row & 7)) << 4);
            cp16(dst, g_b0 + (size_t)(k0 + row) * DIM + g * 8);
        }
    };
    stage_b(0, 0);
    CP_COMMIT();

    // ldmatrix lane constants (verified R7/R8)
    const int aBase = 32 * wm + ((L >> 3) & 1) * 8 + (L & 7);
    const int aG    = L >> 4;
    const int sxa   = aBase & 7;
    const int bBase = 64 * wn + (L >> 4) * 8 + (L & 7);
    const int bG    = (L >> 3) & 1;
    const int sxb   = bBase & 7;
    const uint32_t aAddr0 = sbase + aBase * 256;

    // per-thread row slots r = bi*2+h
    int   nrow[4];
    float rval[4];
    float anx[4], any[4], thr[4];
    #pragma unroll
    for (int bi = 0; bi < 2; ++bi)
        #pragma unroll
        for (int h = 0; h < 2; ++h) {
            int r = bi * 2 + h;
            nrow[r] = n0 + 32 * wm + 16 * bi + 8 * h + (L >> 2);
            rval[r] = 3.0e38f;
            if (PHASE == 2) {
                float2 an = g_an[nrow[r]];
                anx[r] = an.x; any[r] = an.y;
                // thr = best + mmax(n) + slack
                thr[r] = g_bestval[nrow[r]] + an.x * g_bmax[0] +
                         an.y * g_bmax[1] + 0.02f;
            }
        }

    for (int kt = 0; kt < NT; ++kt) {
        const int st = kt & 1;
        const int k0 = kt * BK;

        CP_WAIT0();
        __syncthreads();
        if (kt + 1 < NT) { stage_b(st ^ 1, k0 + BK); CP_COMMIT(); }

        const uint32_t bAddr = sbase + 32768 + st * 32768 + bBase * 256;

        float acc[2][8][4];
        #pragma unroll
        for (int bi = 0; bi < 2; ++bi)
            #pragma unroll
            for (int nb = 0; nb < 8; ++nb)
                #pragma unroll
                for (int c = 0; c < 4; ++c) acc[bi][nb][c] = 0.0f;

        #pragma unroll
        for (int kk = 0; kk < 8; ++kk) {
            uint32_t a[2][4];
            #pragma unroll
            for (int bi = 0; bi < 2; ++bi) {
                uint32_t ad = aAddr0 + bi * 4096 + (((2 * kk + aG) ^ sxa) << 4);
                LDSM_X4(a[bi][0], a[bi][1], a[bi][2], a[bi][3], ad);
            }
            uint32_t b[4][4];
            #pragma unroll
            for (int i = 0; i < 4; ++i) {
                uint32_t bd = bAddr + i * 4096 + (((2 * kk + bG) ^ sxb) << 4);
                LDSM_X4(b[i][0], b[i][1], b[i][2], b[i][3], bd);
            }
            #pragma unroll
            for (int bi = 0; bi < 2; ++bi)
                #pragma unroll
                for (int nb = 0; nb < 8; ++nb) {
                    const uint32_t* q = b[nb >> 1];
                    if (nb & 1) MMA_BF16(acc[bi][nb], a[bi], q[2], q[3]);
                    else        MMA_BF16(acc[bi][nb], a[bi], q[0], q[1]);
                }
        }

        // ---- epilogue ----
        #pragma unroll
        for (int bi = 0; bi < 2; ++bi)
            #pragma unroll
            for (int nb = 0; nb < 8; ++nb) {
                int kc = k0 + 64 * wn + 8 * nb + 2 * (L & 3);
                float2 c2p = __ldg((const float2*)(g_c2 + kc));
                float4 bn4;
                if (PHASE == 2)
                    bn4 = __ldg((const float4*)(g_bn + kc));  // {Bk0,B1k0,Bk1,B1k1}
                #pragma unroll
                for (int h = 0; h < 2; ++h) {
                    int r = bi * 2 + h;
                    float s0 = fmaf(-2.0f, acc[bi][nb][h * 2 + 0], c2p.x);
                    float s1 = fmaf(-2.0f, acc[bi][nb][h * 2 + 1], c2p.y);
                    if (PHASE == 1) {
                        rval[r] = fminf(rval[r], fminf(s0, s1));
                    } else {
                        // margin(n,k) = anx*||b||_k + any*||b1||_k (+ thr folds rest)
                        if (s0 <= fmaf(anx[r], bn4.x, fmaf(any[r], bn4.y, thr[r]))) {
                            int p = atomicAdd(g_cnt, 1);
                            if (p < CAP)
                                g_list[p] = ((uint32_t)nrow[r] << 12) | (uint32_t)kc;
                        }
                        if (s1 <= fmaf(anx[r], bn4.z, fmaf(any[r], bn4.w, thr[r]))) {
                            int p = atomicAdd(g_cnt, 1);
                            if (p < CAP)
                                g_list[p] = ((uint32_t)nrow[r] << 12) | (uint32_t)(kc + 1);
                        }
                    }
                }
            }
    }

    if (PHASE == 1) {
        // CTA merge: 8 slots per row -> g_bestval
        __syncthreads();
        float* rv = (float*)smem;
        #pragma unroll
        for (int bi = 0; bi < 2; ++bi)
            #pragma unroll
            for (int h = 0; h < 2; ++h) {
                int row  = 32 * wm + 16 * bi + 8 * h + (L >> 2);
                int slot = wn * 4 + (L & 3);
                rv[row * 8 + slot] = rval[bi * 2 + h];
            }
        __syncthreads();
        if (tid < BN) {
            float bv = rv[tid * 8];
            #pragma unroll
            for (int c = 1; c < 8; ++c) bv = fminf(bv, rv[tid * 8 + c]);
            g_bestval[n0 + tid] = bv;
        }
    }
}

// ---------------------------------------------------------------------------
// Phase 3: exact fp32 rescoring of candidates; warp per candidate.
// ---------------------------------------------------------------------------
__global__ void exact_kernel(const float* __restrict__ latent,
                             const float* __restrict__ coords) {
    int gw   = (blockIdx.x * blockDim.x + threadIdx.x) >> 5;
    int lane = threadIdx.x & 31;
    int nw   = (gridDim.x * blockDim.x) >> 5;
    int cnt  = g_cnt[0];
    if (cnt > CAP) cnt = CAP;

    for (int i = gw; i < cnt; i += nw) {
        uint32_t pk = g_list[i];
        int n = pk >> 12, k = pk & 4095;
        float4 x = ((const float4*)(latent + (size_t)n * DIM))[lane];
        float4 c = ((const float4*)(coords + (size_t)k * DIM))[lane];
        float d = fmaf(x.x, c.x, fmaf(x.y, c.y, fmaf(x.z, c.z, x.w * c.w)));
        #pragma unroll
        for (int o = 16; o; o >>= 1) d += __shfl_xor_sync(~0u, d, o);
        if (lane == 0) {
            float s = fmaf(-2.0f, d, g_c2[k]);
            unsigned long long key =
                ((unsigned long long)fkey(s) << 32) | (unsigned int)k;
            atomicMin(&g_best[n], key);
        }
    }
}

// ---------------------------------------------------------------------------
extern "C" void kernel_launch(void* const* d_in, const int* in_sizes, int n_in,
                              void* d_out, int out_size) {
    const float* latent;
    const float* coords;
    if (in_sizes[0] == NPTS * DIM) {
        latent = (const float*)d_in[0];
        coords = (const float*)d_in[1];
    } else {
        latent = (const float*)d_in[1];
        coords = (const float*)d_in[0];
    }
    float* out = (float*)d_out;

    const int smem_bytes = 98304;   // A 32K + B 2x32K
    cudaFuncSetAttribute(phase_kernel<1>,
                         cudaFuncAttributeMaxDynamicSharedMemorySize, smem_bytes);
    cudaFuncSetAttribute(phase_kernel<2>,
                         cudaFuncAttributeMaxDynamicSharedMemorySize, smem_bytes);

    init_best_kernel<<<NPTS / 256, 256>>>();
    prep_a<<<NPTS / 8, 256>>>(latent);
    prep_b<<<KC / 8, 256>>>(coords);
    reduce_kernel<<<1, 512>>>();
    phase_kernel<1><<<NPTS / BN, 256, smem_bytes>>>();
    phase_kernel<2><<<NPTS / BN, 256, smem_bytes>>>();
    exact_kernel<<<1024, 256>>>(latent, coords);
    final_kernel<<<NPTS / 256, 256>>>(out);
}

// round 13
// speedup vs baseline: 5.4460x; 1.1459x over previous
#include <cuda_runtime.h>
#include <cuda_bf16.h>
#include <cstdint>

#define NPTS 65536
#define KC   4096
#define DIM  128
#define BN   256          // rows per CTA (amortizes B staging 2x)
#define BK   128
#define NT   (KC / BK)    // 32 tiles, full k-range per CTA
#define CAP  (1 << 24)    // candidate list capacity (16M)

// Device scratch (allocation-free rule)
__device__ __nv_bfloat16 g_a0[NPTS * DIM];
__device__ __nv_bfloat16 g_b0[KC * DIM];
__device__ __align__(16) float2 g_an[NPTS];  // {2||a1||, 2||a0||}
__device__ __align__(16) float2 g_bn[KC];    // {||b||, ||b1||}
__device__ __align__(8)  float  g_c2[KC];    // exact ||b||^2
__device__ float g_bmax[2];                  // {max||b||, max||b1||}
__device__ float g_bestval[NPTS];            // phase-1 approx best
__device__ unsigned long long g_best[NPTS];  // (fkey(score)<<32)|idx
__device__ int g_cnt[1];
__device__ uint32_t g_list[CAP];             // (n<<12)|k

// ---------------------------------------------------------------------------
__device__ __forceinline__ uint32_t smem_u32(const void* p) {
    uint32_t a;
    asm("{ .reg .u64 t; cvta.to.shared.u64 t, %1; cvt.u32.u64 %0, t; }"
        : "=r"(a) : "l"(p));
    return a;
}
__device__ __forceinline__ uint32_t fkey(float f) {      // order-preserving
    uint32_t u = __float_as_uint(f);
    return (u & 0x80000000u) ? ~u : (u | 0x80000000u);
}
#define LDSM_X4(r0, r1, r2, r3, addr) \
    asm volatile("ldmatrix.sync.aligned.m8n8.x4.shared.b16 {%0,%1,%2,%3}, [%4];" \
                 : "=r"(r0), "=r"(r1), "=r"(r2), "=r"(r3) : "r"(addr))
#define MMA_BF16(c, a, b0v, b1v) \
    asm volatile("mma.sync.aligned.m16n8k16.row.col.f32.bf16.bf16.f32 " \
                 "{%0,%1,%2,%3}, {%4,%5,%6,%7}, {%8,%9}, {%0,%1,%2,%3};" \
                 : "+f"((c)[0]), "+f"((c)[1]), "+f"((c)[2]), "+f"((c)[3]) \
                 : "r"((a)[0]), "r"((a)[1]), "r"((a)[2]), "r"((a)[3]), \
                   "r"(b0v), "r"(b1v))
__device__ __forceinline__ void cp16(uint32_t dst, const void* src) {
    asm volatile("cp.async.cg.shared.global [%0], [%1], 16;"
                 :: "r"(dst), "l"(src));
}
#define CP_COMMIT() asm volatile("cp.async.commit_group;" ::: "memory")
#define CP_WAIT0()  asm volatile("cp.async.wait_group 0;" ::: "memory")

// ---------------------------------------------------------------------------
// Prologues (identical math to R12 — validated rel_err 0.0)
// ---------------------------------------------------------------------------
__global__ void prep_a(const float* __restrict__ in) {
    int row  = blockIdx.x * 8 + (threadIdx.x >> 5);
    int lane = threadIdx.x & 31;
    float4 v = ((const float4*)(in + (size_t)row * DIM))[lane];
    float va[4] = {v.x, v.y, v.z, v.w};
    __nv_bfloat16 h[4];
    float n0 = 0.f, n1 = 0.f;
    #pragma unroll
    for (int j = 0; j < 4; ++j) {
        h[j] = __float2bfloat16(va[j]);
        float a0 = __bfloat162float(h[j]);
        float r  = va[j] - a0;
        n0 = fmaf(a0, a0, n0);
        n1 = fmaf(r, r, n1);
    }
    *(uint2*)(g_a0 + (size_t)row * DIM + lane * 4) = *(const uint2*)h;
    #pragma unroll
    for (int o = 16; o; o >>= 1) {
        n0 += __shfl_xor_sync(~0u, n0, o);
        n1 += __shfl_xor_sync(~0u, n1, o);
    }
    if (lane == 0) g_an[row] = make_float2(2.f * sqrtf(n1), 2.f * sqrtf(n0));
}
__global__ void prep_b(const float* __restrict__ in) {
    int row  = blockIdx.x * 8 + (threadIdx.x >> 5);
    int lane = threadIdx.x & 31;
    float4 v = ((const float4*)(in + (size_t)row * DIM))[lane];
    float va[4] = {v.x, v.y, v.z, v.w};
    __nv_bfloat16 h[4];
    float nb = 0.f, n1 = 0.f;
    #pragma unroll
    for (int j = 0; j < 4; ++j) {
        h[j] = __float2bfloat16(va[j]);
        float b0 = __bfloat162float(h[j]);
        float r  = va[j] - b0;
        nb = fmaf(va[j], va[j], nb);
        n1 = fmaf(r, r, n1);
    }
    *(uint2*)(g_b0 + (size_t)row * DIM + lane * 4) = *(const uint2*)h;
    #pragma unroll
    for (int o = 16; o; o >>= 1) {
        nb += __shfl_xor_sync(~0u, nb, o);
        n1 += __shfl_xor_sync(~0u, n1, o);
    }
    if (lane == 0) {
        g_c2[row] = nb;
        g_bn[row] = make_float2(sqrtf(nb), sqrtf(n1));
    }
}
__global__ void reduce_kernel() {
    __shared__ float s0[512], s1[512];
    int t = threadIdx.x;
    float m0 = 0.f, m1 = 0.f;
    for (int k = t; k < KC; k += 512) {
        float2 b = g_bn[k];
        m0 = fmaxf(m0, b.x);
        m1 = fmaxf(m1, b.y);
    }
    s0[t] = m0; s1[t] = m1;
    __syncthreads();
    for (int o = 256; o; o >>= 1) {
        if (t < o) {
            s0[t] = fmaxf(s0[t], s0[t + o]);
            s1[t] = fmaxf(s1[t], s1[t + o]);
        }
        __syncthreads();
    }
    if (t == 0) { g_bmax[0] = s0[0]; g_bmax[1] = s1[0]; g_cnt[0] = 0; }
}
__global__ void init_best_kernel() {
    int i = blockIdx.x * blockDim.x + threadIdx.x;
    if (i < NPTS) g_best[i] = 0xFFFFFFFFFFFFFFFFull;
}
__global__ void final_kernel(float* __restrict__ out) {
    int i = blockIdx.x * blockDim.x + threadIdx.x;
    if (i < NPTS) out[i] = (float)(uint32_t)(g_best[i] & 0xFFFFFFFFull);
}

// ---------------------------------------------------------------------------
// Phase GEMM: 1-pass a0*b0 HMMA, full K=4096 per CTA, BN=256 rows.
// 512 threads = 16 warps, grid 4(M) x 4(N); warp tile 64(M) x 32(N).
// smem: A @0 (64K), B double-buffer @64K/96K, c2 (full K) @128K. 144 KB.
// PHASE=1: per-row min -> g_bestval (direct store, one CTA per row block).
// PHASE=2: identical scores; push (n,k) with s <= best + margin(n,k).
// ---------------------------------------------------------------------------
template <int PHASE>
__global__ __launch_bounds__(512) void phase_kernel() {
    extern __shared__ char smem[];
    const uint32_t sbase = smem_u32(smem);

    const int tid = threadIdx.x;
    const int L   = tid & 31;
    const int wid = tid >> 5;
    const int wm  = wid & 3;        // 4 M groups (64 rows each)
    const int wn  = wid >> 2;       // 4 N groups (32 cols each)
    const int n0  = blockIdx.x * BN;

    // stage A once: 256 rows x 256B, swizzled
    #pragma unroll
    for (int it = 0; it < 8; ++it) {
        int Gi = tid + it * 512;               // 0..4095 granules
        int row = Gi >> 4, g = Gi & 15;
        uint4 v = *((const uint4*)(g_a0 + (size_t)(n0 + row) * DIM) + g);
        *(uint4*)(smem + row * 256 + ((g ^ (row & 7)) << 4)) = v;
    }
    // stage full-K c2 once (16 KB)
    #pragma unroll
    for (int it = 0; it < 2; ++it) {
        int Gi = tid + it * 512;               // 0..1023 float4s
        cp16(sbase + 131072 + Gi * 16, g_c2 + Gi * 4);
    }
    const float* c2s = (const float*)(smem + 131072);

    auto stage_b = [&](int st, int k0) {
        #pragma unroll
        for (int it = 0; it < 4; ++it) {
            int Gi = tid + it * 512;           // 0..2047 granules
            int row = Gi >> 4, g = Gi & 15;
            uint32_t dst = sbase + 65536 + st * 32768 +
                           row * 256 + ((g ^ (row & 7)) << 4);
            cp16(dst, g_b0 + (size_t)(k0 + row) * DIM + g * 8);
        }
    };
    stage_b(0, 0);
    CP_COMMIT();

    // ldmatrix lane constants
    const int aRow = ((L >> 3) & 1) * 8 + (L & 7);
    const int aG   = L >> 4;
    const int sxa  = (L & 7);
    const int bRow = (L >> 4) * 8 + (L & 7);
    const int bG   = (L >> 3) & 1;
    const int sxb  = (L & 7);
    uint32_t aAddrB[4];
    #pragma unroll
    for (int bi = 0; bi < 4; ++bi)
        aAddrB[bi] = sbase + (64 * wm + 16 * bi + aRow) * 256;
    const uint32_t bOff = (32 * wn + bRow) * 256;

    // per-thread rows: nrow[bi][h] = n0 + 64wm + 16bi + 8h + (L>>2)
    float rval[4][2];
    float anx[4][2], any[4][2], thr[4][2];
    #pragma unroll
    for (int bi = 0; bi < 4; ++bi)
        #pragma unroll
        for (int h = 0; h < 2; ++h) {
            rval[bi][h] = 3.0e38f;
            if (PHASE == 2) {
                int nr = n0 + 64 * wm + 16 * bi + 8 * h + (L >> 2);
                float2 an = g_an[nr];
                anx[bi][h] = an.x; any[bi][h] = an.y;
                thr[bi][h] = g_bestval[nr] + an.x * g_bmax[0] +
                             an.y * g_bmax[1] + 0.02f;
            }
        }

    for (int kt = 0; kt < NT; ++kt) {
        const int st = kt & 1;
        const int k0 = kt * BK;

        CP_WAIT0();
        __syncthreads();
        if (kt + 1 < NT) { stage_b(st ^ 1, k0 + BK); CP_COMMIT(); }

        const uint32_t bAddr = sbase + 65536 + st * 32768 + bOff;

        float acc[4][4][4];
        #pragma unroll
        for (int bi = 0; bi < 4; ++bi)
            #pragma unroll
            for (int nb = 0; nb < 4; ++nb)
                #pragma unroll
                for (int c = 0; c < 4; ++c) acc[bi][nb][c] = 0.0f;

        #pragma unroll
        for (int kk = 0; kk < 8; ++kk) {
            uint32_t a[4][4];
            #pragma unroll
            for (int bi = 0; bi < 4; ++bi) {
                uint32_t ad = aAddrB[bi] + (((2 * kk + aG) ^ sxa) << 4);
                LDSM_X4(a[bi][0], a[bi][1], a[bi][2], a[bi][3], ad);
            }
            uint32_t b[2][4];
            #pragma unroll
            for (int i2 = 0; i2 < 2; ++i2) {
                uint32_t bd = bAddr + i2 * 4096 + (((2 * kk + bG) ^ sxb) << 4);
                LDSM_X4(b[i2][0], b[i2][1], b[i2][2], b[i2][3], bd);
            }
            #pragma unroll
            for (int bi = 0; bi < 4; ++bi)
                #pragma unroll
                for (int nb = 0; nb < 4; ++nb) {
                    const uint32_t* q = b[nb >> 1];
                    if (nb & 1) MMA_BF16(acc[bi][nb], a[bi], q[2], q[3]);
                    else        MMA_BF16(acc[bi][nb], a[bi], q[0], q[1]);
                }
        }

        // ---- epilogue ----
        #pragma unroll
        for (int nb = 0; nb < 4; ++nb) {
            int kc = k0 + 32 * wn + 8 * nb + 2 * (L & 3);
            float c2a = c2s[kc], c2b = c2s[kc + 1];
            float4 bn4;
            if (PHASE == 2)
                bn4 = __ldg((const float4*)(g_bn + kc));   // {Bk,B1k,Bk1,B1k1}
            #pragma unroll
            for (int bi = 0; bi < 4; ++bi)
                #pragma unroll
                for (int h = 0; h < 2; ++h) {
                    float s0 = fmaf(-2.0f, acc[bi][nb][h * 2 + 0], c2a);
                    float s1 = fmaf(-2.0f, acc[bi][nb][h * 2 + 1], c2b);
                    if (PHASE == 1) {
                        rval[bi][h] = fminf(rval[bi][h], fminf(s0, s1));
                    } else {
                        int nr = n0 + 64 * wm + 16 * bi + 8 * h + (L >> 2);
                        if (s0 <= fmaf(anx[bi][h], bn4.x,
                                       fmaf(any[bi][h], bn4.y, thr[bi][h]))) {
                            int p = atomicAdd(g_cnt, 1);
                            if (p < CAP)
                                g_list[p] = ((uint32_t)nr << 12) | (uint32_t)kc;
                        }
                        if (s1 <= fmaf(anx[bi][h], bn4.z,
                                       fmaf(any[bi][h], bn4.w, thr[bi][h]))) {
                            int p = atomicAdd(g_cnt, 1);
                            if (p < CAP)
                                g_list[p] = ((uint32_t)nr << 12) | (uint32_t)(kc + 1);
                        }
                    }
                }
        }
    }

    if (PHASE == 1) {
        // CTA merge: 256 rows x 16 slots -> g_bestval (direct store)
        __syncthreads();
        float* rv = (float*)smem;     // 16 KB, reuse A region
        #pragma unroll
        for (int bi = 0; bi < 4; ++bi)
            #pragma unroll
            for (int h = 0; h < 2; ++h) {
                int row  = 64 * wm + 16 * bi + 8 * h + (L >> 2);
                int slot = wn * 4 + (L & 3);
                rv[row * 16 + slot] = rval[bi][h];
            }
        __syncthreads();
        if (tid < BN) {
            float bv = rv[tid * 16];
            #pragma unroll
            for (int c = 1; c < 16; ++c) bv = fminf(bv, rv[tid * 16 + c]);
            g_bestval[n0 + tid] = bv;
        }
    }
}

// ---------------------------------------------------------------------------
// Phase 3: exact fp32 rescoring of candidates; warp per candidate.
// ---------------------------------------------------------------------------
__global__ void exact_kernel(const float* __restrict__ latent,
                             const float* __restrict__ coords) {
    int gw   = (blockIdx.x * blockDim.x + threadIdx.x) >> 5;
    int lane = threadIdx.x & 31;
    int nw   = (gridDim.x * blockDim.x) >> 5;
    int cnt  = g_cnt[0];
    if (cnt > CAP) cnt = CAP;

    for (int i = gw; i < cnt; i += nw) {
        uint32_t pk = g_list[i];
        int n = pk >> 12, k = pk & 4095;
        float4 x = ((const float4*)(latent + (size_t)n * DIM))[lane];
        float4 c = ((const float4*)(coords + (size_t)k * DIM))[lane];
        float d = fmaf(x.x, c.x, fmaf(x.y, c.y, fmaf(x.z, c.z, x.w * c.w)));
        #pragma unroll
        for (int o = 16; o; o >>= 1) d += __shfl_xor_sync(~0u, d, o);
        if (lane == 0) {
            float s = fmaf(-2.0f, d, g_c2[k]);
            unsigned long long key =
                ((unsigned long long)fkey(s) << 32) | (unsigned int)k;
            atomicMin(&g_best[n], key);
        }
    }
}

// ---------------------------------------------------------------------------
extern "C" void kernel_launch(void* const* d_in, const int* in_sizes, int n_in,
                              void* d_out, int out_size) {
    const float* latent;
    const float* coords;
    if (in_sizes[0] == NPTS * DIM) {
        latent = (const float*)d_in[0];
        coords = (const float*)d_in[1];
    } else {
        latent = (const float*)d_in[1];
        coords = (const float*)d_in[0];
    }
    float* out = (float*)d_out;

    const int smem_bytes = 131072 + 16384;   // A 64K + B 2x32K + c2 16K
    cudaFuncSetAttribute(phase_kernel<1>,
                         cudaFuncAttributeMaxDynamicSharedMemorySize, smem_bytes);
    cudaFuncSetAttribute(phase_kernel<2>,
                         cudaFuncAttributeMaxDynamicSharedMemorySize, smem_bytes);

    init_best_kernel<<<NPTS / 256, 256>>>();
    prep_a<<<NPTS / 8, 256>>>(latent);
    prep_b<<<KC / 8, 256>>>(coords);
    reduce_kernel<<<1, 512>>>();
    phase_kernel<1><<<NPTS / BN, 512, smem_bytes>>>();
    phase_kernel<2><<<NPTS / BN, 512, smem_bytes>>>();
    exact_kernel<<<1024, 256>>>(latent, coords);
    final_kernel<<<NPTS / 256, 256>>>(out);
}